// round 4
// baseline (speedup 1.0000x reference)
#include <cuda_runtime.h>
#include <cuda_bf16.h>
#include <math.h>

// Problem constants
#define BATCH   128
#define NNODE   64
#define TDIM    256
#define KIN     320          // N + T
#define HDIM    256
#define ODIM    128
#define EPG     2016         // edges per graph
#define TEDGE   (BATCH*EPG)  // 258048
#define MROWS   (BATCH*NNODE)// 8192
#define NPAD    520          // padded concat-head width (514 used)
#define PSTR    515          // odd smem row stride for edge kernel

// ---------------- device scratch (static, allocation-free) ----------------
__device__ float g_xcat[MROWS * KIN];     // 10.5 MB
__device__ float g_z   [MROWS * HDIM];    //  8.4 MB
__device__ float g_h   [MROWS * HDIM];    //  8.4 MB
__device__ float g_Wcat[HDIM * NPAD];     //  0.53 MB
__device__ float g_P   [MROWS * NPAD];    // 17.0 MB
__device__ float g_simnum[TEDGE];         //  1.0 MB
__device__ float g_partials[BATCH];
__device__ float g_invS;

// ---------------- prep: concat node features -------------------------------
__global__ void k_prep_xcat(const float* __restrict__ topo,
                            const float* __restrict__ temp) {
    int idx = blockIdx.x * blockDim.x + threadIdx.x;
    if (idx >= MROWS * KIN) return;
    int m = idx / KIN, k = idx - m * KIN;
    g_xcat[idx] = (k < NNODE) ? topo[m * NNODE + k] : temp[m * TDIM + (k - NNODE)];
}

// ---------------- prep: pack head weights [256 x 520] ----------------------
__global__ void k_prep_wcat(const float* __restrict__ Wm,
                            const float* __restrict__ Wv,
                            const float* __restrict__ Ww) {
    int idx = blockIdx.x * blockDim.x + threadIdx.x;
    if (idx >= HDIM * NPAD) return;
    int k = idx / NPAD, n = idx - k * NPAD;
    float v = 0.f;
    if      (n < 128) v = Wm[k * ODIM + n];
    else if (n < 256) v = Wm[(HDIM + k) * ODIM + (n - 128)];
    else if (n < 384) v = Wv[k * ODIM + (n - 256)];
    else if (n < 512) v = Wv[(HDIM + k) * ODIM + (n - 384)];
    else if (n == 512) v = Ww[k];
    else if (n == 513) v = Ww[HDIM + k];
    g_Wcat[idx] = v;
}

// ---------------- tiled SGEMM: C[MxN] = A[MxK] @ B[KxN] --------------------
// 128x128 tile, 8x8 per thread, BK=8. M % 128 == 0, K % 8 == 0, N % 4 == 0.
__global__ __launch_bounds__(256)
void sgemm128(const float* __restrict__ A, const float* __restrict__ B,
              float* __restrict__ C, int M, int N, int K) {
    __shared__ float As[8][128];
    __shared__ float Bs[8][128];
    const int bx = blockIdx.x, by = blockIdx.y;
    const int tid = threadIdx.x;
    const int tx = tid & 15, ty = tid >> 4;
    const int rowC = by * 128 + ty * 8;
    const int colC = bx * 128 + tx * 8;

    const int aRow = tid >> 1, aK = (tid & 1) * 4;
    const int bK   = tid >> 5, bCol = (tid & 31) * 4;

    const float* Ag = A + (by * 128 + aRow) * K + aK;

    float acc[8][8];
#pragma unroll
    for (int i = 0; i < 8; i++)
#pragma unroll
        for (int j = 0; j < 8; j++) acc[i][j] = 0.f;

    for (int k0 = 0; k0 < K; k0 += 8) {
        float4 av = *(const float4*)(Ag + k0);
        As[aK + 0][aRow] = av.x; As[aK + 1][aRow] = av.y;
        As[aK + 2][aRow] = av.z; As[aK + 3][aRow] = av.w;
        int bc = bx * 128 + bCol;
        float4 bv = make_float4(0.f, 0.f, 0.f, 0.f);
        if (bc < N) bv = *(const float4*)(B + (k0 + bK) * N + bc);
        *(float4*)&Bs[bK][bCol] = bv;
        __syncthreads();
#pragma unroll
        for (int kk = 0; kk < 8; kk++) {
            float4 a0 = *(float4*)&As[kk][ty * 8];
            float4 a1 = *(float4*)&As[kk][ty * 8 + 4];
            float4 b0 = *(float4*)&Bs[kk][tx * 8];
            float4 b1 = *(float4*)&Bs[kk][tx * 8 + 4];
            float ar[8] = {a0.x,a0.y,a0.z,a0.w,a1.x,a1.y,a1.z,a1.w};
            float br[8] = {b0.x,b0.y,b0.z,b0.w,b1.x,b1.y,b1.z,b1.w};
#pragma unroll
            for (int i = 0; i < 8; i++)
#pragma unroll
                for (int j = 0; j < 8; j++) acc[i][j] += ar[i] * br[j];
        }
        __syncthreads();
    }
#pragma unroll
    for (int i = 0; i < 8; i++) {
        int r = rowC + i;
#pragma unroll
        for (int j = 0; j < 8; j += 4) {
            int c = colC + j;
            if (c < N) {
                float4 o = make_float4(acc[i][j], acc[i][j+1], acc[i][j+2], acc[i][j+3]);
                *(float4*)(C + r * N + c) = o;
            }
        }
    }
}

// ---------------- prefix-mean + ReLU: h from z -----------------------------
__global__ __launch_bounds__(256)
void k_prefix(const float* __restrict__ bgnn) {
    int b = blockIdx.x, f = threadIdx.x;   // 128 blocks x 256 threads
    float bias = bgnn[f];
    float s = 0.f;
#pragma unroll 4
    for (int j = 0; j < NNODE; j++) {
        float agg = (j > 0) ? (s / (float)j) : 0.f;
        float hv = agg + bias;
        g_h[(b * NNODE + j) * HDIM + f] = fmaxf(hv, 0.f);
        s += g_z[(b * NNODE + j) * HDIM + f];
    }
}

// ---------------- per-edge pass: sim * exp(logit), partial sums ------------
__global__ __launch_bounds__(256)
void k_edges(const float* __restrict__ bm, const float* __restrict__ bv,
             const float* __restrict__ bw, const float* __restrict__ gum) {
    extern __shared__ float sP[];                 // 64 * 515 floats
    __shared__ float sBm[128], sBv[128], red[256];
    const int b = blockIdx.x, tid = threadIdx.x;

    for (int idx = tid; idx < NNODE * 514; idx += 256) {
        int n = idx / 514, c = idx - n * 514;
        sP[n * PSTR + c] = g_P[(b * NNODE + n) * NPAD + c];
    }
    if (tid < 128) { sBm[tid] = bm[tid]; sBv[tid] = bv[tid]; }
    const float bww = bw[0];
    __syncthreads();

    float lsum = 0.f;
    for (int e = tid; e < EPG; e += 256) {
        // invert triangular index: base(i) = i*63 - i*(i-1)/2
        int i = (int)((127.0f - sqrtf((float)(16129 - 8 * e))) * 0.5f);
        while ((i + 1) * 63 - ((i + 1) * i) / 2 <= e) ++i;
        while (i * 63 - (i * (i - 1)) / 2 > e)        --i;
        int base = i * 63 - (i * (i - 1)) / 2;
        int j = e - base + i + 1;

        const float* ps = sP + i * PSTR;
        const float* pd = sP + j * PSTR;
        float acc = 0.f;
#pragma unroll 4
        for (int k = 0; k < ODIM; k++) {
            float m = ps[k]       + pd[128 + k] + sBm[k];
            float t = ps[256 + k] + pd[384 + k] + sBv[k];
            // stable softplus: max(t,0) + log(1+exp(-|t|))
            float sp = fmaxf(t, 0.f) + __logf(1.f + __expf(-fabsf(t)));
            float v  = sp + 1e-6f + 1e-8f;
            acc += __fdividef(m * m, v);
        }
        float sim = __expf(acc * (-1.0f / 256.0f));   // exp(-0.5*mean)
        float wl  = ps[512] + pd[513] + bww;
        float w   = __fdividef(1.f, 1.f + __expf(-wl));
        float u   = gum[b * EPG + e];
        float gmb = -__logf(-logf(u));                // inner log full precision
        float num = __expf((w + gmb) * 2.0f);         // /TEMPERATURE(0.5)
        g_simnum[b * EPG + e] = sim * num;
        lsum += num;
    }
    red[tid] = lsum;
    __syncthreads();
    for (int s2 = 128; s2 > 0; s2 >>= 1) {
        if (tid < s2) red[tid] += red[tid + s2];
        __syncthreads();
    }
    if (tid == 0) g_partials[b] = red[0];
}

// ---------------- reduce partials -> 1/S -----------------------------------
__global__ void k_reduce() {
    __shared__ float red[128];
    int t = threadIdx.x;
    red[t] = g_partials[t];
    __syncthreads();
    for (int s = 64; s > 0; s >>= 1) {
        if (t < s) red[t] += red[t + s];
        __syncthreads();
    }
    if (t == 0) g_invS = 1.0f / red[0];
}

// ---------------- scatter to dense adjacency -------------------------------
__global__ void k_final(float* __restrict__ out) {
    int idx = blockIdx.x * blockDim.x + threadIdx.x;
    if (idx >= BATCH * NNODE * NNODE) return;
    int b = idx >> 12;
    int r = (idx >> 6) & 63;
    int c = idx & 63;
    float v = 0.f;
    if (r < c) {
        int e = r * 63 - (r * (r - 1)) / 2 + (c - r - 1);
        v = g_simnum[b * EPG + e] * g_invS;
    }
    out[idx] = v;
}

// ---------------- launch ----------------------------------------------------
extern "C" void kernel_launch(void* const* d_in, const int* in_sizes, int n_in,
                              void* d_out, int out_size) {
    const float* topo  = (const float*)d_in[0];
    const float* temp  = (const float*)d_in[1];
    const float* gum   = (const float*)d_in[2];
    const float* Wgnn  = (const float*)d_in[3];
    const float* bgnn  = (const float*)d_in[4];
    const float* Wm    = (const float*)d_in[5];
    const float* bmn   = (const float*)d_in[6];
    const float* Wv    = (const float*)d_in[7];
    const float* bvr   = (const float*)d_in[8];
    const float* Ww    = (const float*)d_in[9];
    const float* bww   = (const float*)d_in[10];
    float* out = (float*)d_out;

    static float *pz = nullptr, *ph = nullptr, *pxc = nullptr, *pwc = nullptr, *pp = nullptr;
    if (!pz) {
        cudaGetSymbolAddress((void**)&pxc, g_xcat);
        cudaGetSymbolAddress((void**)&pz,  g_z);
        cudaGetSymbolAddress((void**)&ph,  g_h);
        cudaGetSymbolAddress((void**)&pwc, g_Wcat);
        cudaGetSymbolAddress((void**)&pp,  g_P);
        cudaFuncSetAttribute(k_edges, cudaFuncAttributeMaxDynamicSharedMemorySize,
                             NNODE * PSTR * (int)sizeof(float));
    }

    // 1. assemble inputs
    k_prep_xcat<<<(MROWS * KIN + 255) / 256, 256>>>(topo, temp);
    k_prep_wcat<<<(HDIM * NPAD + 255) / 256, 256>>>(Wm, Wv, Ww);

    // 2. z = x_cat @ W_gnn   (8192 x 320 x 256)
    sgemm128<<<dim3(HDIM / 128, MROWS / 128), 256>>>(pxc, Wgnn, pz, MROWS, HDIM, KIN);

    // 3. h = relu(prefix(z)/j + b)
    k_prefix<<<BATCH, 256>>>(bgnn);

    // 4. P = h @ Wcat        (8192 x 256 x 520)
    sgemm128<<<dim3((NPAD + 127) / 128, MROWS / 128), 256>>>(ph, pwc, pp, MROWS, NPAD, HDIM);

    // 5. per-edge sim * exp(logit), block partial sums
    k_edges<<<BATCH, 256, NNODE * PSTR * (int)sizeof(float)>>>(bmn, bvr, bww, gum);

    // 6. global 1/sum
    k_reduce<<<1, 128>>>();

    // 7. dense adjacency
    k_final<<<(BATCH * NNODE * NNODE + 255) / 256, 256>>>(out);
}

// round 5
// speedup vs baseline: 1.4914x; 1.4914x over previous
#include <cuda_runtime.h>
#include <cuda_bf16.h>
#include <math.h>

// Problem constants
#define BATCH   128
#define NNODE   64
#define TDIM    256
#define KIN     320          // N + T
#define HDIM    256
#define ODIM    128
#define EPG     2016         // edges per graph
#define TEDGE   (BATCH*EPG)  // 258048
#define MROWS   (BATCH*NNODE)// 8192
#define PW      512          // packed mean/var head width
#define PSTR    517          // smem row stride in edge kernel (517 mod 32 = 5, odd)

// ---------------- device scratch (static, allocation-free) ----------------
__device__ float g_h   [MROWS * HDIM];    //  8.4 MB
__device__ float g_Wcat[HDIM * PW];       //  0.5 MB  (mean/var heads packed)
__device__ float g_P   [MROWS * PW];      // 16.8 MB  (per-node mean/var projections)
__device__ float g_Pw  [MROWS * 2];       //  64 KB   (per-node W_w projections)
__device__ float g_simnum[TEDGE];         //  1.0 MB
__device__ float g_partials[BATCH];
__device__ float g_invS;

// ---------------- prep: pack mean/var head weights [256 x 512] -------------
__global__ void k_prep_wcat(const float* __restrict__ Wm,
                            const float* __restrict__ Wv) {
    int idx = blockIdx.x * blockDim.x + threadIdx.x;
    if (idx >= HDIM * PW) return;
    int k = idx >> 9, n = idx & 511;
    float v;
    if      (n < 128) v = Wm[k * ODIM + n];
    else if (n < 256) v = Wm[(HDIM + k) * ODIM + (n - 128)];
    else if (n < 384) v = Wv[k * ODIM + (n - 256)];
    else              v = Wv[(HDIM + k) * ODIM + (n - 384)];
    g_Wcat[idx] = v;
}

// ---------------- GEMM1 fused: h = relu(prefixmean(xcat @ Wgnn) + b) -------
// A[8192 x 320] assembled on the fly from topo/temp. 128x128 tile, grid (2,64).
// Epilogue: per-column exclusive prefix-mean over each 64-row graph + ReLU.
__global__ __launch_bounds__(256)
void gemm1_fused(const float* __restrict__ topo, const float* __restrict__ temp,
                 const float* __restrict__ W, const float* __restrict__ bias) {
    extern __shared__ float Cs[];              // 128 * 129 floats (66 KB)
    __shared__ float As[8][128];
    __shared__ float Bs[8][128];
    const int bx = blockIdx.x, by = blockIdx.y;
    const int tid = threadIdx.x;
    const int tx = tid & 15, ty = tid >> 4;

    const int aRow = tid >> 1, aK4 = (tid & 1) * 4;
    const int bK   = tid >> 5, bCol = (tid & 31) * 4;
    const int m    = by * 128 + aRow;

    float acc[8][8];
#pragma unroll
    for (int i = 0; i < 8; i++)
#pragma unroll
        for (int j = 0; j < 8; j++) acc[i][j] = 0.f;

    for (int k0 = 0; k0 < KIN; k0 += 8) {
        int k = k0 + aK4;
        float4 av = (k < NNODE)
            ? *(const float4*)(topo + m * NNODE + k)
            : *(const float4*)(temp + m * TDIM + (k - NNODE));
        As[aK4 + 0][aRow] = av.x; As[aK4 + 1][aRow] = av.y;
        As[aK4 + 2][aRow] = av.z; As[aK4 + 3][aRow] = av.w;
        float4 bv = *(const float4*)(W + (k0 + bK) * HDIM + bx * 128 + bCol);
        *(float4*)&Bs[bK][bCol] = bv;
        __syncthreads();
#pragma unroll
        for (int kk = 0; kk < 8; kk++) {
            float4 a0 = *(float4*)&As[kk][ty * 8];
            float4 a1 = *(float4*)&As[kk][ty * 8 + 4];
            float4 b0 = *(float4*)&Bs[kk][tx * 8];
            float4 b1 = *(float4*)&Bs[kk][tx * 8 + 4];
            float ar[8] = {a0.x,a0.y,a0.z,a0.w,a1.x,a1.y,a1.z,a1.w};
            float br[8] = {b0.x,b0.y,b0.z,b0.w,b1.x,b1.y,b1.z,b1.w};
#pragma unroll
            for (int i = 0; i < 8; i++)
#pragma unroll
                for (int j = 0; j < 8; j++) acc[i][j] += ar[i] * br[j];
        }
        __syncthreads();
    }

    // stage tile to smem for column scans
#pragma unroll
    for (int i = 0; i < 8; i++)
#pragma unroll
        for (int j = 0; j < 8; j++)
            Cs[(ty * 8 + i) * 129 + tx * 8 + j] = acc[i][j];
    __syncthreads();

    // prefix-mean + ReLU: 256 threads = 128 cols x 2 graphs
    const int col = tid & 127, g = tid >> 7;
    const int cg  = bx * 128 + col;
    const float bv = bias[cg];
    float s = 0.f;
    float* hout = g_h + ((by * 2 + g) * NNODE) * HDIM + cg;
#pragma unroll 4
    for (int j = 0; j < NNODE; j++) {
        float agg = (j > 0) ? (s / (float)j) : 0.f;
        hout[j * HDIM] = fmaxf(agg + bv, 0.f);
        s += Cs[(g * NNODE + j) * 129 + col];
    }
}

// ---------------- tiled SGEMM: C[MxN] = A[MxK] @ B[KxN], exact tiles -------
__global__ __launch_bounds__(256)
void sgemm128(const float* __restrict__ A, const float* __restrict__ B,
              float* __restrict__ C, int N, int K) {
    __shared__ float As[8][128];
    __shared__ float Bs[8][128];
    const int bx = blockIdx.x, by = blockIdx.y;
    const int tid = threadIdx.x;
    const int tx = tid & 15, ty = tid >> 4;

    const int aRow = tid >> 1, aK4 = (tid & 1) * 4;
    const int bK   = tid >> 5, bCol = (tid & 31) * 4;

    const float* Ag = A + (by * 128 + aRow) * K + aK4;
    const float* Bg = B + bK * N + bx * 128 + bCol;

    float acc[8][8];
#pragma unroll
    for (int i = 0; i < 8; i++)
#pragma unroll
        for (int j = 0; j < 8; j++) acc[i][j] = 0.f;

    for (int k0 = 0; k0 < K; k0 += 8) {
        float4 av = *(const float4*)(Ag + k0);
        As[aK4 + 0][aRow] = av.x; As[aK4 + 1][aRow] = av.y;
        As[aK4 + 2][aRow] = av.z; As[aK4 + 3][aRow] = av.w;
        float4 bv = *(const float4*)(Bg + k0 * N);
        *(float4*)&Bs[bK][bCol] = bv;
        __syncthreads();
#pragma unroll
        for (int kk = 0; kk < 8; kk++) {
            float4 a0 = *(float4*)&As[kk][ty * 8];
            float4 a1 = *(float4*)&As[kk][ty * 8 + 4];
            float4 b0 = *(float4*)&Bs[kk][tx * 8];
            float4 b1 = *(float4*)&Bs[kk][tx * 8 + 4];
            float ar[8] = {a0.x,a0.y,a0.z,a0.w,a1.x,a1.y,a1.z,a1.w};
            float br[8] = {b0.x,b0.y,b0.z,b0.w,b1.x,b1.y,b1.z,b1.w};
#pragma unroll
            for (int i = 0; i < 8; i++)
#pragma unroll
                for (int j = 0; j < 8; j++) acc[i][j] += ar[i] * br[j];
        }
        __syncthreads();
    }
    const int rowC = by * 128 + ty * 8;
    const int colC = bx * 128 + tx * 8;
#pragma unroll
    for (int i = 0; i < 8; i++)
#pragma unroll
        for (int j = 0; j < 8; j += 4) {
            float4 o = make_float4(acc[i][j], acc[i][j+1], acc[i][j+2], acc[i][j+3]);
            *(float4*)(C + (rowC + i) * N + colC + j) = o;
        }
}

// ---------------- skinny W_w projections: g_Pw[m][0..1] --------------------
__global__ __launch_bounds__(256)
void k_ww(const float* __restrict__ Ww) {
    int wid = threadIdx.x >> 5, lane = threadIdx.x & 31;
    int m = blockIdx.x * 8 + wid;               // grid = 1024
    const float* hrow = g_h + m * HDIM;
    float s0 = 0.f, s1 = 0.f;
#pragma unroll
    for (int k = lane; k < HDIM; k += 32) {
        float hv = hrow[k];
        s0 += hv * Ww[k];
        s1 += hv * Ww[HDIM + k];
    }
#pragma unroll
    for (int o = 16; o; o >>= 1) {
        s0 += __shfl_down_sync(0xffffffffu, s0, o);
        s1 += __shfl_down_sync(0xffffffffu, s1, o);
    }
    if (lane == 0) { g_Pw[m * 2] = s0; g_Pw[m * 2 + 1] = s1; }
}

// ---------------- per-edge pass: sim * exp(logit), partial sums ------------
__global__ __launch_bounds__(512)
void k_edges(const float* __restrict__ bm, const float* __restrict__ bv,
             const float* __restrict__ bw, const float* __restrict__ gum) {
    extern __shared__ float sP[];               // 64 * 517 floats
    __shared__ float sW[128], sBm[128], sBv[128], red[512];
    const int b = blockIdx.x, tid = threadIdx.x;

    const float* src = g_P + b * (NNODE * PW);
    for (int idx = tid; idx < NNODE * PW; idx += 512) {
        int n = idx >> 9, c = idx & 511;
        sP[n * PSTR + c] = src[idx];
    }
    if (tid < 128)                 sW[tid]        = g_Pw[b * 128 + tid];
    else if (tid < 256)            sBm[tid - 128] = bm[tid - 128];
    else if (tid < 384)            sBv[tid - 256] = bv[tid - 256];
    const float bww = bw[0];
    __syncthreads();

    float lsum = 0.f;
    for (int e = tid; e < EPG; e += 512) {
        // invert triangular index: base(i) = i*63 - i*(i-1)/2
        int i = (int)((127.0f - sqrtf((float)(16129 - 8 * e))) * 0.5f);
        while ((i + 1) * 63 - ((i + 1) * i) / 2 <= e) ++i;
        while (i * 63 - (i * (i - 1)) / 2 > e)        --i;
        int base = i * 63 - (i * (i - 1)) / 2;
        int j = e - base + i + 1;

        const float* ps = sP + i * PSTR;
        const float* pd = sP + j * PSTR;
        float acc = 0.f;
#pragma unroll 4
        for (int k = 0; k < ODIM; k++) {
            float m = ps[k]       + pd[128 + k] + sBm[k];
            float t = ps[256 + k] + pd[384 + k] + sBv[k];
            float sp = fmaxf(t, 0.f) + __logf(1.f + __expf(-fabsf(t)));
            float v  = sp + 1e-6f + 1e-8f;
            acc += __fdividef(m * m, v);
        }
        float sim = __expf(acc * (-1.0f / 256.0f));   // exp(-0.5*mean)
        float wl  = sW[2 * i] + sW[2 * j + 1] + bww;
        float w   = __fdividef(1.f, 1.f + __expf(-wl));
        float u   = gum[b * EPG + e];
        float gmb = -__logf(-logf(u));
        float num = __expf((w + gmb) * 2.0f);         // /TEMPERATURE(0.5)
        g_simnum[b * EPG + e] = sim * num;
        lsum += num;
    }
    red[tid] = lsum;
    __syncthreads();
    for (int s2 = 256; s2 > 0; s2 >>= 1) {
        if (tid < s2) red[tid] += red[tid + s2];
        __syncthreads();
    }
    if (tid == 0) g_partials[b] = red[0];
}

// ---------------- reduce partials -> 1/S -----------------------------------
__global__ void k_reduce() {
    __shared__ float red[128];
    int t = threadIdx.x;
    red[t] = g_partials[t];
    __syncthreads();
    for (int s = 64; s > 0; s >>= 1) {
        if (t < s) red[t] += red[t + s];
        __syncthreads();
    }
    if (t == 0) g_invS = 1.0f / red[0];
}

// ---------------- scatter to dense adjacency -------------------------------
__global__ void k_final(float* __restrict__ out) {
    int idx = blockIdx.x * blockDim.x + threadIdx.x;
    if (idx >= BATCH * NNODE * NNODE) return;
    int b = idx >> 12;
    int r = (idx >> 6) & 63;
    int c = idx & 63;
    float v = 0.f;
    if (r < c) {
        int e = r * 63 - (r * (r - 1)) / 2 + (c - r - 1);
        v = g_simnum[b * EPG + e] * g_invS;
    }
    out[idx] = v;
}

// ---------------- launch ----------------------------------------------------
extern "C" void kernel_launch(void* const* d_in, const int* in_sizes, int n_in,
                              void* d_out, int out_size) {
    const float* topo  = (const float*)d_in[0];
    const float* temp  = (const float*)d_in[1];
    const float* gum   = (const float*)d_in[2];
    const float* Wgnn  = (const float*)d_in[3];
    const float* bgnn  = (const float*)d_in[4];
    const float* Wm    = (const float*)d_in[5];
    const float* bmn   = (const float*)d_in[6];
    const float* Wv    = (const float*)d_in[7];
    const float* bvr   = (const float*)d_in[8];
    const float* Ww    = (const float*)d_in[9];
    const float* bww   = (const float*)d_in[10];
    float* out = (float*)d_out;

    static float *ph = nullptr, *pwc = nullptr, *pp = nullptr;
    static int g1_smem = 128 * 129 * (int)sizeof(float);      // 66048
    static int ed_smem = NNODE * PSTR * (int)sizeof(float);   // 132352
    if (!ph) {
        cudaGetSymbolAddress((void**)&ph,  g_h);
        cudaGetSymbolAddress((void**)&pwc, g_Wcat);
        cudaGetSymbolAddress((void**)&pp,  g_P);
        cudaFuncSetAttribute(gemm1_fused, cudaFuncAttributeMaxDynamicSharedMemorySize, g1_smem);
        cudaFuncSetAttribute(k_edges,     cudaFuncAttributeMaxDynamicSharedMemorySize, ed_smem);
    }

    // 1. pack head weights (independent of everything downstream of GEMM1)
    k_prep_wcat<<<(HDIM * PW + 255) / 256, 256>>>(Wm, Wv);

    // 2. h = relu(prefixmean(xcat @ Wgnn) + b)   — fused concat + GEMM + scan
    gemm1_fused<<<dim3(HDIM / 128, MROWS / 128), 256, g1_smem>>>(topo, temp, Wgnn, bgnn);

    // 3. P = h @ Wcat  (8192 x 512 x 256, exact tiles, 2 waves)
    sgemm128<<<dim3(PW / 128, MROWS / 128), 256>>>(ph, pwc, pp, PW, HDIM);

    // 4. skinny W_w projections
    k_ww<<<MROWS / 8, 256>>>(Ww);

    // 5. per-edge sim * exp(logit), block partial sums
    k_edges<<<BATCH, 512, ed_smem>>>(bmn, bvr, bww, gum);

    // 6. global 1/sum
    k_reduce<<<1, 128>>>();

    // 7. dense adjacency
    k_final<<<(BATCH * NNODE * NNODE + 255) / 256, 256>>>(out);
}

// round 8
// speedup vs baseline: 2.0491x; 1.3740x over previous
#include <cuda_runtime.h>
#include <cuda_bf16.h>
#include <math.h>
#include <cstdint>

// Problem constants
#define BATCH   128
#define NNODE   64
#define TDIM    256
#define KIN     320          // N + T
#define HDIM    256
#define ODIM    128
#define EPG     2016         // edges per graph
#define TEDGE   (BATCH*EPG)  // 258048
#define MROWS   (BATCH*NNODE)// 8192
#define PW      512          // packed mean/var head width
#define PSTR    517          // smem row stride in edge kernel

// mma staging: k-chunk 64, row stride 36 b32 (conflict-free frag loads)
#define KC      64
#define BSTR    36           // b32 per staged row
#define REG_U32 (128 * BSTR) // 4608 u32 per tile region
#define MM_SMEM (4 * REG_U32 * 4)  // 73728 bytes

// ---------------- device scratch (static, allocation-free) ----------------
__device__ float g_h     [MROWS * HDIM];   //  8.4 MB
__device__ float g_WgnnT [HDIM * KIN];     //  0.33 MB  (Wgnn^T: [256][320])
__device__ float g_WcatT [PW * HDIM];      //  0.52 MB  (packed heads^T: [512][256])
__device__ float g_P     [MROWS * PW];     // 16.8 MB
__device__ float g_Pw    [MROWS * 2];      //  64 KB
__device__ float g_simnum[TEDGE];          //  1.0 MB
__device__ float g_partials[BATCH];
__device__ float g_invS;

// ==================== mma.sync helpers (baseline PTX, sm_80+) ==============
__device__ __forceinline__ void mma_bf16(float* c, const uint32_t* a, const uint32_t* b) {
    asm volatile(
        "mma.sync.aligned.m16n8k16.row.col.f32.bf16.bf16.f32 "
        "{%0,%1,%2,%3}, {%4,%5,%6,%7}, {%8,%9}, {%0,%1,%2,%3};"
        : "+f"(c[0]), "+f"(c[1]), "+f"(c[2]), "+f"(c[3])
        : "r"(a[0]), "r"(a[1]), "r"(a[2]), "r"(a[3]), "r"(b[0]), "r"(b[1]));
}

// split two floats into packed bf16x2 hi and lo (low 16 bits = first element)
__device__ __forceinline__ void cvt2(float a, float b, uint32_t& hi, uint32_t& lo) {
    __nv_bfloat16 ha = __float2bfloat16_rn(a), hb = __float2bfloat16_rn(b);
    float ra = a - __bfloat162float(ha), rb = b - __bfloat162float(hb);
    __nv_bfloat16 la = __float2bfloat16_rn(ra), lb = __float2bfloat16_rn(rb);
    hi = ((uint32_t)__bfloat16_as_ushort(hb) << 16) | (uint32_t)__bfloat16_as_ushort(ha);
    lo = ((uint32_t)__bfloat16_as_ushort(lb) << 16) | (uint32_t)__bfloat16_as_ushort(la);
}

// stage 128 rows x 64 f32 columns -> hi/lo bf16x2 tiles [128][BSTR u32]
__device__ __forceinline__ void stage64(const float* __restrict__ g, int gstride,
                                        uint32_t* __restrict__ sh,
                                        uint32_t* __restrict__ sl, int tid) {
    const int row = tid >> 1, cg = (tid & 1) * 16;      // 16 b32 = 32 floats
    const float* src = g + row * gstride + cg * 2;
    uint32_t* dh = sh + row * BSTR + cg;
    uint32_t* dl = sl + row * BSTR + cg;
#pragma unroll
    for (int q = 0; q < 8; ++q) {
        float4 v = *(const float4*)(src + q * 4);
        uint32_t h0, l0, h1, l1;
        cvt2(v.x, v.y, h0, l0);
        cvt2(v.z, v.w, h1, l1);
        dh[2 * q] = h0; dh[2 * q + 1] = h1;
        dl[2 * q] = l0; dl[2 * q + 1] = l1;
    }
}

// one k=64 chunk of bf16x2-compensated mma into acc[2][8][4]
__device__ __forceinline__ void chunk_mma(const uint32_t* __restrict__ sAh,
                                          const uint32_t* __restrict__ sAl,
                                          const uint32_t* __restrict__ sBh,
                                          const uint32_t* __restrict__ sBl,
                                          int wm, int wn, int lane,
                                          float acc[2][8][4]) {
    const int g = lane >> 2, t = lane & 3;
#pragma unroll
    for (int kb = 0; kb < 4; ++kb) {
        const int kc = kb * 8 + t;
        uint32_t Ah[2][4], Al[2][4], Bh[8][2], Bl[8][2];
#pragma unroll
        for (int i = 0; i < 2; ++i) {
            int r = (wm * 32 + 16 * i + g) * BSTR + kc;
            Ah[i][0] = sAh[r];              Ah[i][1] = sAh[r + 8 * BSTR];
            Ah[i][2] = sAh[r + 4];          Ah[i][3] = sAh[r + 8 * BSTR + 4];
            Al[i][0] = sAl[r];              Al[i][1] = sAl[r + 8 * BSTR];
            Al[i][2] = sAl[r + 4];          Al[i][3] = sAl[r + 8 * BSTR + 4];
        }
#pragma unroll
        for (int j = 0; j < 8; ++j) {
            int r = (wn * 64 + 8 * j + g) * BSTR + kc;
            Bh[j][0] = sBh[r]; Bh[j][1] = sBh[r + 4];
            Bl[j][0] = sBl[r]; Bl[j][1] = sBl[r + 4];
        }
#pragma unroll
        for (int i = 0; i < 2; ++i)
#pragma unroll
            for (int j = 0; j < 8; ++j) {
                mma_bf16(acc[i][j], Ah[i], Bh[j]);   // hi*hi
                mma_bf16(acc[i][j], Ah[i], Bl[j]);   // hi*lo
                mma_bf16(acc[i][j], Al[i], Bh[j]);   // lo*hi
            }
    }
}

// ---------------- prep: transpose Wgnn + pack/transpose heads --------------
__global__ void k_prep_T(const float* __restrict__ Wgnn, const float* __restrict__ Wm,
                         const float* __restrict__ Wv) {
    int idx = blockIdx.x * blockDim.x + threadIdx.x;
    if (idx < HDIM * KIN) {
        int n = idx / KIN, k = idx - n * KIN;
        g_WgnnT[idx] = Wgnn[k * HDIM + n];
        return;
    }
    idx -= HDIM * KIN;
    if (idx >= PW * HDIM) return;
    int n = idx >> 8, k = idx & 255;
    float v;
    if      (n < 128) v = Wm[k * ODIM + n];
    else if (n < 256) v = Wm[(HDIM + k) * ODIM + (n - 128)];
    else if (n < 384) v = Wv[k * ODIM + (n - 256)];
    else              v = Wv[(HDIM + k) * ODIM + (n - 384)];
    g_WcatT[idx] = v;
}

// ====== GEMM1 (mma.sync bf16x2): h = relu(prefixmean(xcat@Wgnn)+b) =========
// grid (2, 64), 256 threads. K=320 in 5 chunks of 64. Fused scan epilogue.
__global__ __launch_bounds__(256)
void gemm1_mma(const float* __restrict__ topo, const float* __restrict__ temp,
               const float* __restrict__ bias) {
    extern __shared__ uint32_t sm[];
    uint32_t *sAh = sm, *sAl = sm + REG_U32, *sBh = sm + 2 * REG_U32, *sBl = sm + 3 * REG_U32;
    const int tid = threadIdx.x, lane = tid & 31, wid = tid >> 5;
    const int wm = wid >> 1, wn = wid & 1;
    const int bx = blockIdx.x, by = blockIdx.y;
    const int m0 = by * 128, n0 = bx * 128;

    float acc[2][8][4];
#pragma unroll
    for (int i = 0; i < 2; ++i)
#pragma unroll
        for (int j = 0; j < 8; ++j)
#pragma unroll
            for (int q = 0; q < 4; ++q) acc[i][j][q] = 0.f;

#pragma unroll 1
    for (int c = 0; c < 5; ++c) {
        __syncthreads();
        if (c == 0) stage64(topo + m0 * NNODE, NNODE, sAh, sAl, tid);
        else        stage64(temp + m0 * TDIM + (c - 1) * KC, TDIM, sAh, sAl, tid);
        stage64(g_WgnnT + n0 * KIN + c * KC, KIN, sBh, sBl, tid);
        __syncthreads();
        chunk_mma(sAh, sAl, sBh, sBl, wm, wn, lane, acc);
    }

    // epilogue: fragments -> smem scan buffer (aliased over staging tiles)
    __syncthreads();
    float* sD = (float*)sm;                 // 128 x 129 floats (66 KB <= 72 KB)
    const int g = lane >> 2, t = lane & 3;
#pragma unroll
    for (int i = 0; i < 2; ++i) {
        int r0 = wm * 32 + 16 * i + g;
#pragma unroll
        for (int j = 0; j < 8; ++j) {
            int cc = wn * 64 + 8 * j + t * 2;
            sD[r0 * 129 + cc]       = acc[i][j][0];
            sD[r0 * 129 + cc + 1]   = acc[i][j][1];
            sD[(r0 + 8) * 129 + cc]     = acc[i][j][2];
            sD[(r0 + 8) * 129 + cc + 1] = acc[i][j][3];
        }
    }
    __syncthreads();

    // prefix-mean + ReLU: 256 threads = 128 cols x 2 graphs
    {
        const int col = tid & 127, gph = tid >> 7;
        const float bv = bias[n0 + col];
        float s = 0.f;
        float* hout = g_h + ((by * 2 + gph) * NNODE) * HDIM + n0 + col;
#pragma unroll 4
        for (int j = 0; j < NNODE; ++j) {
            float agg = (j > 0) ? (s / (float)j) : 0.f;
            hout[j * HDIM] = fmaxf(agg + bv, 0.f);
            s += sD[(gph * NNODE + j) * 129 + col];
        }
    }
}

// ====== GEMM2 (mma.sync bf16x2): P = h @ WcatT^T ===========================
// grid (4, 64), 256 threads. K=256 in 4 chunks of 64.
__global__ __launch_bounds__(256)
void gemm2_mma() {
    extern __shared__ uint32_t sm[];
    uint32_t *sAh = sm, *sAl = sm + REG_U32, *sBh = sm + 2 * REG_U32, *sBl = sm + 3 * REG_U32;
    const int tid = threadIdx.x, lane = tid & 31, wid = tid >> 5;
    const int wm = wid >> 1, wn = wid & 1;
    const int bx = blockIdx.x, by = blockIdx.y;
    const int m0 = by * 128, n0 = bx * 128;

    float acc[2][8][4];
#pragma unroll
    for (int i = 0; i < 2; ++i)
#pragma unroll
        for (int j = 0; j < 8; ++j)
#pragma unroll
            for (int q = 0; q < 4; ++q) acc[i][j][q] = 0.f;

#pragma unroll 1
    for (int c = 0; c < 4; ++c) {
        __syncthreads();
        stage64(g_h + m0 * HDIM + c * KC, HDIM, sAh, sAl, tid);
        stage64(g_WcatT + n0 * HDIM + c * KC, HDIM, sBh, sBl, tid);
        __syncthreads();
        chunk_mma(sAh, sAl, sBh, sBl, wm, wn, lane, acc);
    }

    // epilogue: fragments -> g_P (float2 stores, 8B aligned: cols even)
    const int g = lane >> 2, t = lane & 3;
#pragma unroll
    for (int i = 0; i < 2; ++i) {
        int r0 = m0 + wm * 32 + 16 * i + g;
#pragma unroll
        for (int j = 0; j < 8; ++j) {
            int cc = n0 + wn * 64 + 8 * j + t * 2;
            *(float2*)(g_P + r0 * PW + cc)       = make_float2(acc[i][j][0], acc[i][j][1]);
            *(float2*)(g_P + (r0 + 8) * PW + cc) = make_float2(acc[i][j][2], acc[i][j][3]);
        }
    }
}

// ---------------- skinny W_w projections: g_Pw[m][0..1] --------------------
__global__ __launch_bounds__(256)
void k_ww(const float* __restrict__ Ww) {
    int wid = threadIdx.x >> 5, lane = threadIdx.x & 31;
    int m = blockIdx.x * 8 + wid;               // grid = 1024
    const float* hrow = g_h + m * HDIM;
    float s0 = 0.f, s1 = 0.f;
#pragma unroll
    for (int it = 0; it < 2; ++it) {
        int k = it * 128 + lane * 4;
        float4 hv = *(const float4*)(hrow + k);
        float4 w0 = *(const float4*)(Ww + k);
        float4 w1 = *(const float4*)(Ww + HDIM + k);
        s0 += hv.x * w0.x + hv.y * w0.y + hv.z * w0.z + hv.w * w0.w;
        s1 += hv.x * w1.x + hv.y * w1.y + hv.z * w1.z + hv.w * w1.w;
    }
#pragma unroll
    for (int o = 16; o; o >>= 1) {
        s0 += __shfl_down_sync(0xffffffffu, s0, o);
        s1 += __shfl_down_sync(0xffffffffu, s1, o);
    }
    if (lane == 0) { g_Pw[m * 2] = s0; g_Pw[m * 2 + 1] = s1; }
}

// ---------------- per-edge pass: sim * exp(logit), partial sums ------------
__global__ __launch_bounds__(512)
void k_edges(const float* __restrict__ bm, const float* __restrict__ bv,
             const float* __restrict__ bw, const float* __restrict__ gum) {
    extern __shared__ float sP[];               // 64 * 517 floats
    __shared__ float sW[128], sBm[128], sBv[128], red[512];
    const int b = blockIdx.x, tid = threadIdx.x;

    const float* src = g_P + b * (NNODE * PW);
    for (int idx = tid; idx < NNODE * PW; idx += 512) {
        int n = idx >> 9, c = idx & 511;
        sP[n * PSTR + c] = src[idx];
    }
    if (tid < 128)                 sW[tid]        = g_Pw[b * 128 + tid];
    else if (tid < 256)            sBm[tid - 128] = bm[tid - 128];
    else if (tid < 384)            sBv[tid - 256] = bv[tid - 256];
    const float bww = bw[0];
    __syncthreads();

    float lsum = 0.f;
    for (int e = tid; e < EPG; e += 512) {
        int i = (int)((127.0f - sqrtf((float)(16129 - 8 * e))) * 0.5f);
        while ((i + 1) * 63 - ((i + 1) * i) / 2 <= e) ++i;
        while (i * 63 - (i * (i - 1)) / 2 > e)        --i;
        int base = i * 63 - (i * (i - 1)) / 2;
        int j = e - base + i + 1;

        const float* ps = sP + i * PSTR;
        const float* pd = sP + j * PSTR;
        float acc = 0.f;
#pragma unroll 4
        for (int k = 0; k < ODIM; k++) {
            float m = ps[k]       + pd[128 + k] + sBm[k];
            float t = ps[256 + k] + pd[384 + k] + sBv[k];
            float sp = fmaxf(t, 0.f) + __logf(1.f + __expf(-fabsf(t)));
            float v  = sp + 1e-6f + 1e-8f;
            acc += __fdividef(m * m, v);
        }
        float sim = __expf(acc * (-1.0f / 256.0f));
        float wl  = sW[2 * i] + sW[2 * j + 1] + bww;
        float w   = __fdividef(1.f, 1.f + __expf(-wl));
        float u   = gum[b * EPG + e];
        float gmb = -__logf(-logf(u));
        float num = __expf((w + gmb) * 2.0f);
        g_simnum[b * EPG + e] = sim * num;
        lsum += num;
    }
    red[tid] = lsum;
    __syncthreads();
    for (int s2 = 256; s2 > 0; s2 >>= 1) {
        if (tid < s2) red[tid] += red[tid + s2];
        __syncthreads();
    }
    if (tid == 0) g_partials[b] = red[0];
}

// ---------------- reduce partials -> 1/S -----------------------------------
__global__ void k_reduce() {
    __shared__ float red[128];
    int t = threadIdx.x;
    red[t] = g_partials[t];
    __syncthreads();
    for (int s = 64; s > 0; s >>= 1) {
        if (t < s) red[t] += red[t + s];
        __syncthreads();
    }
    if (t == 0) g_invS = 1.0f / red[0];
}

// ---------------- scatter to dense adjacency -------------------------------
__global__ void k_final(float* __restrict__ out) {
    int idx = blockIdx.x * blockDim.x + threadIdx.x;
    if (idx >= BATCH * NNODE * NNODE) return;
    int b = idx >> 12;
    int r = (idx >> 6) & 63;
    int c = idx & 63;
    float v = 0.f;
    if (r < c) {
        int e = r * 63 - (r * (r - 1)) / 2 + (c - r - 1);
        v = g_simnum[b * EPG + e] * g_invS;
    }
    out[idx] = v;
}

// ---------------- launch ----------------------------------------------------
extern "C" void kernel_launch(void* const* d_in, const int* in_sizes, int n_in,
                              void* d_out, int out_size) {
    const float* topo  = (const float*)d_in[0];
    const float* temp  = (const float*)d_in[1];
    const float* gum   = (const float*)d_in[2];
    const float* Wgnn  = (const float*)d_in[3];
    const float* bgnn  = (const float*)d_in[4];
    const float* Wm    = (const float*)d_in[5];
    const float* bmn   = (const float*)d_in[6];
    const float* Wv    = (const float*)d_in[7];
    const float* bvr   = (const float*)d_in[8];
    const float* Ww    = (const float*)d_in[9];
    const float* bww   = (const float*)d_in[10];
    float* out = (float*)d_out;

    static bool init_done = false;
    static int ed_smem = NNODE * PSTR * (int)sizeof(float);   // 132352
    if (!init_done) {
        cudaFuncSetAttribute(gemm1_mma, cudaFuncAttributeMaxDynamicSharedMemorySize, MM_SMEM);
        cudaFuncSetAttribute(gemm2_mma, cudaFuncAttributeMaxDynamicSharedMemorySize, MM_SMEM);
        cudaFuncSetAttribute(k_edges,   cudaFuncAttributeMaxDynamicSharedMemorySize, ed_smem);
        init_done = true;
    }

    // 1. transpose/pack weights
    k_prep_T<<<(HDIM * KIN + PW * HDIM + 255) / 256, 256>>>(Wgnn, Wm, Wv);

    // 2. h = relu(prefixmean(xcat @ Wgnn) + b)  — mma.sync bf16x2, fused scan
    gemm1_mma<<<dim3(HDIM / 128, MROWS / 128), 256, MM_SMEM>>>(topo, temp, bgnn);

    // 3. P = h @ Wcat  — mma.sync bf16x2
    gemm2_mma<<<dim3(PW / 128, MROWS / 128), 256, MM_SMEM>>>();

    // 4. skinny W_w projections
    k_ww<<<MROWS / 8, 256>>>(Ww);

    // 5. per-edge sim * exp(logit), block partial sums
    k_edges<<<BATCH, 512, ed_smem>>>(bmn, bvr, bww, gum);

    // 6. global 1/sum
    k_reduce<<<1, 128>>>();

    // 7. dense adjacency
    k_final<<<(BATCH * NNODE * NNODE + 255) / 256, 256>>>(out);
}